// round 12
// baseline (speedup 1.0000x reference)
#include <cuda_runtime.h>
#include <cuda_bf16.h>
#include <cstdint>

// BarrierNet via mma.sync (HMMA) split-precision bf16, sm_80-compatible PTX.
// Layer1 (5->128) as ONE m16n8k16 ([xh|xl]x[wh|wh]) + one m16n8k8 (xh x wl);
// D fragments relu'd/split/repacked in registers as layer2 A fragments.
// Layer2 (128->64) 3-term split bf16 m16n8k16, term-round interleaved.
// Warp tile: 16 rows x 64 outputs (small acc => 3 CTAs/SM, 24 warps/SM).
// Persistent: 444 blocks loop over 128-row tiles; weights staged once.

__device__ __forceinline__ uint32_t smem_u32(const void* p) {
    uint32_t a;
    asm("{ .reg .u64 t; cvta.to.shared.u64 t, %1; cvt.u32.u64 %0, t; }" : "=r"(a) : "l"(p));
    return a;
}
__device__ __forceinline__ void ldmx4(uint32_t& r0, uint32_t& r1, uint32_t& r2, uint32_t& r3, uint32_t a) {
    asm volatile("ldmatrix.sync.aligned.m8n8.x4.shared.b16 {%0,%1,%2,%3}, [%4];"
                 : "=r"(r0), "=r"(r1), "=r"(r2), "=r"(r3) : "r"(a));
}
__device__ __forceinline__ void ldmx2(uint32_t& r0, uint32_t& r1, uint32_t a) {
    asm volatile("ldmatrix.sync.aligned.m8n8.x2.shared.b16 {%0,%1}, [%2];"
                 : "=r"(r0), "=r"(r1) : "r"(a));
}
__device__ __forceinline__ void mma16(float* c, const uint32_t* a, const uint32_t* b) {
    asm volatile("mma.sync.aligned.m16n8k16.row.col.f32.bf16.bf16.f32 "
                 "{%0,%1,%2,%3}, {%4,%5,%6,%7}, {%8,%9}, {%0,%1,%2,%3};"
                 : "+f"(c[0]), "+f"(c[1]), "+f"(c[2]), "+f"(c[3])
                 : "r"(a[0]), "r"(a[1]), "r"(a[2]), "r"(a[3]), "r"(b[0]), "r"(b[1]));
}
__device__ __forceinline__ void mma8(float* c, const uint32_t* a, uint32_t b) {
    asm volatile("mma.sync.aligned.m16n8k8.row.col.f32.bf16.bf16.f32 "
                 "{%0,%1,%2,%3}, {%4,%5}, {%6}, {%0,%1,%2,%3};"
                 : "+f"(c[0]), "+f"(c[1]), "+f"(c[2]), "+f"(c[3])
                 : "r"(a[0]), "r"(a[1]), "r"(b));
}
// pack two f32 -> bf16x2: first asm operand -> HIGH half
__device__ __forceinline__ uint32_t cvt2(float hi, float lo) {
    uint32_t r;
    asm("cvt.rn.bf16x2.f32 %0, %1, %2;" : "=r"(r) : "f"(hi), "f"(lo));
    return r;
}
__device__ __forceinline__ float lo_f(uint32_t p) { return __uint_as_float(p << 16); }
__device__ __forceinline__ float hi_f(uint32_t p) { return __uint_as_float(p & 0xFFFF0000u); }

static constexpr int TILE_M = 128;

__global__ __launch_bounds__(256, 3) void barriernet_mma_kernel(
    const float* __restrict__ x,
    const float* __restrict__ mean_, const float* __restrict__ std_,
    const float* __restrict__ w1,  const float* __restrict__ b1,
    const float* __restrict__ w21, const float* __restrict__ b21,
    const float* __restrict__ w22, const float* __restrict__ b22,
    const float* __restrict__ w31, const float* __restrict__ b31,
    const float* __restrict__ w32, const float* __restrict__ b32,
    float2* __restrict__ out, int B, int numTiles)
{
    __shared__ __align__(16) float s_x[128][8];       // 4KB: x0..x4, 1, 0, 0
    __shared__ __align__(16) uint4 s_w1h[128], s_w1l[128];   // [n][k8] bf16x2x4
    __shared__ __align__(16) uint4 s_w2h[64][16], s_w2l[64][16]; // [n][chunk] swizzled
    __shared__ __align__(16) float4 s_ep[64];         // (b2, w3row0, w3row1, 0)
    __shared__ float s_b3[4], s_ms[8];

    const int t = threadIdx.x;

    // ---- stage weights ONCE per block ----
    if (t < 128) {
        float v[8];
#pragma unroll
        for (int i = 0; i < 5; i++) v[i] = w1[t * 5 + i];
        v[5] = b1[t]; v[6] = 0.f; v[7] = 0.f;
        uint4 h, l;
        h.x = cvt2(v[1], v[0]); l.x = cvt2(v[1] - hi_f(h.x), v[0] - lo_f(h.x));
        h.y = cvt2(v[3], v[2]); l.y = cvt2(v[3] - hi_f(h.y), v[2] - lo_f(h.y));
        h.z = cvt2(v[5], v[4]); l.z = cvt2(v[5] - hi_f(h.z), v[4] - lo_f(h.z));
        h.w = 0u;               l.w = 0u;
        s_w1h[t] = h; s_w1l[t] = l;
    }
    for (int i = t; i < 64 * 16; i += 256) {
        const int n = i >> 4, c = i & 15;
        const float* src = (n < 32) ? (w21 + n * 128 + c * 8)
                                    : (w22 + (n - 32) * 128 + c * 8);
        uint4 h, l;
        h.x = cvt2(src[1], src[0]); l.x = cvt2(src[1] - hi_f(h.x), src[0] - lo_f(h.x));
        h.y = cvt2(src[3], src[2]); l.y = cvt2(src[3] - hi_f(h.y), src[2] - lo_f(h.y));
        h.z = cvt2(src[5], src[4]); l.z = cvt2(src[5] - hi_f(h.z), src[4] - lo_f(h.z));
        h.w = cvt2(src[7], src[6]); l.w = cvt2(src[7] - hi_f(h.w), src[6] - lo_f(h.w));
        const int cs = c ^ (n & 7);
        s_w2h[n][cs] = h; s_w2l[n][cs] = l;
    }
    if (t < 64) {
        s_ep[t] = (t < 32) ? make_float4(b21[t], w31[t], w31[32 + t], 0.f)
                           : make_float4(b22[t - 32], w32[t - 32], w32[t], 0.f);
    }
    if (t < 4) s_b3[t] = (t < 2) ? b31[t] : b32[t - 2];
    if (t >= 8 && t < 16) s_ms[t - 8] = (t < 12) ? mean_[t - 8] : std_[t - 12];

    const int wid = t >> 5, lane = t & 31;
    const int g = lane >> 2, tig = lane & 3;
    const int rb = wid * 16;
    const uint32_t w1h_base = smem_u32(s_w1h), w1l_base = smem_u32(s_w1l);
    const uint32_t w2h_base = smem_u32(s_w2h), w2l_base = smem_u32(s_w2l);
    const uint32_t nrow  = (uint32_t)((lane & 7) + ((lane & 16) >> 1));
    const uint32_t klane = (uint32_t)((lane >> 3) & 1);
    const int rl = rb + tig * 8 + g;     // valid for tig < 2

    for (int tile = blockIdx.x; tile < numTiles; tile += gridDim.x) {
        const int tbase = tile * TILE_M;
        __syncthreads();   // previous tile fully consumed s_x
        // ---- stage x (padded, bias column at k=5) ----
        for (int i = t; i < 128 * 8; i += 256) {
            const int r = i >> 3, k = i & 7;
            float v;
            if (k < 5) { const int gr = min(tbase + r, B - 1); v = x[(size_t)gr * 5 + k]; }
            else v = (k == 5) ? 1.0f : 0.0f;
            s_x[r][k] = v;
        }
        __syncthreads();

        // ---- x fragments (rows g, g+8; k = tig*2, tig*2+1) ----
        uint32_t xh[2], xl[2];
        {
            const float2 v0 = *(const float2*)&s_x[rb + g][tig * 2];
            const float2 v1 = *(const float2*)&s_x[rb + g + 8][tig * 2];
            xh[0] = cvt2(v0.y, v0.x);
            xl[0] = cvt2(v0.y - hi_f(xh[0]), v0.x - lo_f(xh[0]));
            xh[1] = cvt2(v1.y, v1.x);
            xl[1] = cvt2(v1.y - hi_f(xh[1]), v1.x - lo_f(xh[1]));
        }

        float acc[8][4];
#pragma unroll
        for (int nf = 0; nf < 8; nf++)
#pragma unroll
            for (int q = 0; q < 4; q++) acc[nf][q] = 0.f;

#pragma unroll
        for (int j = 0; j < 8; j++) {
            // ---- layer 1 chunk j: h[rows][16j..16j+15] ----
            uint32_t wh[2], wl[2];
            {
                const uint32_t a = (uint32_t)((j * 16 + (lane & 15)) * 16);
                ldmx2(wh[0], wh[1], w1h_base + a);
                ldmx2(wl[0], wl[1], w1l_base + a);
            }
            uint32_t Ah[4], Al[4];
            {
                const uint32_t A2[4] = { xh[0], xh[1], xl[0], xl[1] };
                float d[2][4];
#pragma unroll
                for (int nf = 0; nf < 2; nf++) {
                    d[nf][0] = d[nf][1] = d[nf][2] = d[nf][3] = 0.f;
                    const uint32_t B2[2] = { wh[nf], wh[nf] };
                    mma16(d[nf], A2, B2);       // xh*wh + xl*wh in one HMMA
                    mma8(d[nf], xh, wl[nf]);    // + xh*wl
#pragma unroll
                    for (int q = 0; q < 4; q++) d[nf][q] = fmaxf(d[nf][q], 0.f);
                }
                // D(layer1) -> A(layer2) fragment identity
                Ah[0] = cvt2(d[0][1], d[0][0]);
                Al[0] = cvt2(d[0][1] - hi_f(Ah[0]), d[0][0] - lo_f(Ah[0]));
                Ah[1] = cvt2(d[0][3], d[0][2]);
                Al[1] = cvt2(d[0][3] - hi_f(Ah[1]), d[0][2] - lo_f(Ah[1]));
                Ah[2] = cvt2(d[1][1], d[1][0]);
                Al[2] = cvt2(d[1][1] - hi_f(Ah[2]), d[1][0] - lo_f(Ah[2]));
                Ah[3] = cvt2(d[1][3], d[1][2]);
                Al[3] = cvt2(d[1][3] - hi_f(Ah[3]), d[1][2] - lo_f(Ah[3]));
            }

            // ---- layer 2: two halves; loads hoisted, term-rounds interleaved ----
#pragma unroll
            for (int half = 0; half < 2; half++) {
                uint32_t bh[2][2][2], bl[2][2][2];   // [pp][frag][reg]
#pragma unroll
                for (int pp = 0; pp < 2; pp++) {
                    const uint32_t n = nrow + (uint32_t)((half * 2 + pp) * 16);
                    const uint32_t a = (n << 8) + ((((uint32_t)(2 * j) + klane) ^ (n & 7)) << 4);
                    ldmx4(bh[pp][0][0], bh[pp][0][1], bh[pp][1][0], bh[pp][1][1], w2h_base + a);
                    ldmx4(bl[pp][0][0], bl[pp][0][1], bl[pp][1][0], bl[pp][1][1], w2l_base + a);
                }
                // 3 term-rounds of 4 independent MMAs each
#pragma unroll
                for (int term = 0; term < 3; term++) {
#pragma unroll
                    for (int pp = 0; pp < 2; pp++)
#pragma unroll
                        for (int f = 0; f < 2; f++) {
                            const int ai = (half * 2 + pp) * 2 + f;
                            const uint32_t* A = (term == 1) ? Al : Ah;
                            const uint32_t* Bf = (term == 2) ? bl[pp][f] : bh[pp][f];
                            mma16(acc[ai], A, Bf);
                        }
                }
            }
        }

        // ---- epilogue: bias+relu, layer-3 dots, quad reduction, QP ----
        float P[2][4];
#pragma unroll
        for (int o = 0; o < 2; o++) {
            float pax = 0.f, pay = 0.f, pbx = 0.f, pby = 0.f;
#pragma unroll
            for (int nf = 0; nf < 8; nf++) {
                const int n0 = nf * 8 + tig * 2;
                const float4 e0 = s_ep[n0];
                const float4 e1 = s_ep[n0 + 1];
                const float y0 = fmaxf(acc[nf][o * 2 + 0] + e0.x, 0.f);
                const float y1 = fmaxf(acc[nf][o * 2 + 1] + e1.x, 0.f);
                if (nf < 4) {
                    pax = fmaf(y0, e0.y, fmaf(y1, e1.y, pax));
                    pay = fmaf(y0, e0.z, fmaf(y1, e1.z, pay));
                } else {
                    pbx = fmaf(y0, e0.y, fmaf(y1, e1.y, pbx));
                    pby = fmaf(y0, e0.z, fmaf(y1, e1.z, pby));
                }
            }
            P[o][0] = pax; P[o][1] = pay; P[o][2] = pbx; P[o][3] = pby;
        }
#pragma unroll
        for (int o = 0; o < 2; o++)
#pragma unroll
            for (int c = 0; c < 4; c++) {
                P[o][c] += __shfl_xor_sync(0xFFFFFFFFu, P[o][c], 1);
                P[o][c] += __shfl_xor_sync(0xFFFFFFFFu, P[o][c], 2);
            }

        // lane tig<2 handles slot o=tig: row = rb + tig*8 + g
        if (tig < 2) {
            const float uax = P[tig][0], uay = P[tig][1];
            const float ubx = P[tig][2], uby = P[tig][3];
            const int gr = tbase + rl;
            if (gr < B) {
                const float px = s_x[rl][0] * s_ms[4] + s_ms[0];
                const float py = s_x[rl][1] * s_ms[5] + s_ms[1];
                const float th = s_x[rl][2] * s_ms[6] + s_ms[2];
                const float v  = s_x[rl][3] * s_ms[7] + s_ms[3];
                float s, c;
                sincosf(th, &s, &c);
                const float dx = px - 40.0f, dy = py - 15.0f;
                const float barrier = dx * dx + dy * dy - 36.0f;
                const float bdot = 2.0f * dx * v * c + 2.0f * dy * v * s;
                const float Lf2b = 2.0f * v * v;
                const float g1 = -(-2.0f * dx * v * s + 2.0f * dy * v * c);
                const float g2 = -(2.0f * dx * c + 2.0f * dy * s);

                const float u0x = -(uax + s_b3[0]);
                const float u0y = -(uay + s_b3[1]);
                const float z1 = ubx + s_b3[2];
                const float z2 = uby + s_b3[3];
                const float x32_0 = 4.0f / (1.0f + expf(-z1));
                const float x32_1 = 4.0f / (1.0f + expf(-z2));

                const float hq   = Lf2b + (x32_0 + x32_1) * bdot + x32_0 * x32_1 * barrier;
                const float viol = g1 * u0x + g2 * u0y - hq;
                const float gg   = g1 * g1 + g2 * g2;
                const float lam  = fmaxf(viol, 0.f) / (gg + 1e-12f);

                out[gr] = make_float2(u0x - lam * g1, u0y - lam * g2);
            }
        }
    }
}

extern "C" void kernel_launch(void* const* d_in, const int* in_sizes, int n_in,
                              void* d_out, int out_size) {
    const float* x     = (const float*)d_in[0];
    const float* mean_ = (const float*)d_in[2];
    const float* std_  = (const float*)d_in[3];
    const float* w1    = (const float*)d_in[4];
    const float* b1    = (const float*)d_in[5];
    const float* w21   = (const float*)d_in[6];
    const float* b21   = (const float*)d_in[7];
    const float* w22   = (const float*)d_in[8];
    const float* b22   = (const float*)d_in[9];
    const float* w31   = (const float*)d_in[10];
    const float* b31   = (const float*)d_in[11];
    const float* w32   = (const float*)d_in[12];
    const float* b32   = (const float*)d_in[13];

    const int B = in_sizes[0] / 5;
    const int numTiles = (B + TILE_M - 1) / TILE_M;
    const int blocks = 444;   // 3 CTAs/SM x 148 SMs, persistent over tiles
    barriernet_mma_kernel<<<blocks, 256>>>(x, mean_, std_, w1, b1, w21, b21,
                                           w22, b22, w31, b31, w32, b32,
                                           (float2*)d_out, B, numTiles);
}